// round 14
// baseline (speedup 1.0000x reference)
#include <cuda_runtime.h>
#include <cuda_fp16.h>
#include <cuda_bf16.h>
#include <cstdint>

#define NN 100000
#define EE 1600000
#define SCAN_B 1024
#define NB ((NN + SCAN_B - 1) / SCAN_B)   // 98
#define NTILES (NN / 16)                  // 6250 (NN divisible by 16)
#define WCAP 96                           // per-warp smem edge-cache capacity

typedef unsigned long long u64;
typedef unsigned int u32;

// ---------------- scratch (device globals; no allocation allowed) ----------
// A operand in 16-row-tile-major fragment layout:
// addr(row, slot) = (row>>4)*512 + (slot>>2)*64 + (row&15)*4 + (slot&3)
__device__ uint4 g_ap[NN * 32];            // h fragments (GEMM A operand, layers 1..4)
__device__ uint4 g_apx[NN * 32];           // x fragments (input projection source)
__device__ uint4 g_bfrag[5 * 16 * 8 * 32]; // W fragments: {bh0,bh1,bl0,bl1} per lane
__device__ uint2 g_h2h[NN * 32];           // fp16 copy of h2 rows
__device__ float g_as2[NN * 2];            // att-src dot, per N-half partial
__device__ float g_ad2[NN * 2];            // att-dst dot, per N-half partial
__device__ uint2 g_ews[EE];                // fallback {w bits, src} (deg > WCAP only)
__device__ int   g_deg[NN];
__device__ int   g_incl[NN];
__device__ int   g_cursor[NN];
__device__ int   g_rowptr[NN + 1];
__device__ int   g_srcs[EE];
__device__ int   g_bsums[128];

// ---------------- small helpers --------------------------------------------
__device__ __forceinline__ u32 bf2(float a, float b) {
    __nv_bfloat162 t = __floats2bfloat162_rn(a, b);
    return *reinterpret_cast<u32*>(&t);
}
__device__ __forceinline__ u32 hf2(float a, float b) {
    __half2 t = __floats2half2_rn(a, b);
    return *reinterpret_cast<u32*>(&t);
}
__device__ __forceinline__ float bf_res(float v) {   // residual after bf16-hi
    return v - __bfloat162float(__float2bfloat16_rn(v));
}
__device__ __forceinline__ size_t ap_idx(int row, int slot) {
    return (size_t)(row >> 4) * 512 + (size_t)((slot >> 2) << 6)
         + (size_t)((row & 15) << 2) + (size_t)(slot & 3);
}

__device__ __forceinline__ uint4 pack_row_frag(u32 hx, u32 hy, u32 lx, u32 ly, int lane) {
    const int src0 = ((lane >> 2) << 2) + ((lane & 3) >> 1);  // kw>>1
    const int sel = lane & 1;                                  // kw&1
    u32 h0a = __shfl_sync(0xffffffffu, hx, src0);
    u32 h0b = __shfl_sync(0xffffffffu, hy, src0);
    u32 h1a = __shfl_sync(0xffffffffu, hx, src0 + 2);
    u32 h1b = __shfl_sync(0xffffffffu, hy, src0 + 2);
    u32 l0a = __shfl_sync(0xffffffffu, lx, src0);
    u32 l0b = __shfl_sync(0xffffffffu, ly, src0);
    u32 l1a = __shfl_sync(0xffffffffu, lx, src0 + 2);
    u32 l1b = __shfl_sync(0xffffffffu, ly, src0 + 2);
    uint4 r;
    r.x = sel ? h0b : h0a;
    r.y = sel ? h1b : h1a;
    r.z = sel ? l0b : l0a;
    r.w = sel ? l1b : l1a;
    return r;
}

__device__ __forceinline__ void mma16816(
    float& c0, float& c1, float& c2, float& c3,
    u32 a0, u32 a1, u32 a2, u32 a3, u32 b0, u32 b1)
{
    asm volatile(
        "mma.sync.aligned.m16n8k16.row.col.f32.bf16.bf16.f32 "
        "{%0,%1,%2,%3}, {%4,%5,%6,%7}, {%8,%9}, {%0,%1,%2,%3};"
        : "+f"(c0), "+f"(c1), "+f"(c2), "+f"(c3)
        : "r"(a0), "r"(a1), "r"(a2), "r"(a3), "r"(b0), "r"(b1));
}

// ---------------- fused setup: W fragments + x conversion -------------------
__global__ __launch_bounds__(256) void k_setup(
    const float* __restrict__ x,
    const float* __restrict__ W_in, const float* __restrict__ Wl)
{
    const int bid = blockIdx.x;
    const int tid = threadIdx.x;
    if (bid < 80) {
        int idx = bid * 256 + tid;                 // over 20480
        int lane = idx & 31;
        int ks = (idx >> 5) & 7;
        int nb = (idx >> 8) & 15;
        int l = idx >> 12;
        int g = lane >> 2;
        int t = lane & 3;
        int n = nb * 8 + g;
        int kw = ks * 8 + t;
        const float* W = (l == 0) ? W_in : (Wl + (size_t)(l - 1) * 16384);
        float v00 = W[(2 * kw) * 128 + n];
        float v01 = W[(2 * kw + 1) * 128 + n];
        float v10 = W[(2 * kw + 8) * 128 + n];
        float v11 = W[(2 * kw + 9) * 128 + n];
        uint4 f;
        f.x = bf2(v00, v01);
        f.y = bf2(v10, v11);
        f.z = bf2(bf_res(v00), bf_res(v01));
        f.w = bf2(bf_res(v10), bf_res(v11));
        g_bfrag[idx] = f;
    } else {
        int row = ((bid - 80) << 3) + (tid >> 5);  // 8 rows per block
        int lane = tid & 31;
        if (row < NN) {
            float4 v = ((const float4*)x)[(size_t)row * 32 + lane];
            u32 hx = bf2(v.x, v.y), hy = bf2(v.z, v.w);
            u32 lx = bf2(bf_res(v.x), bf_res(v.y)), ly = bf2(bf_res(v.z), bf_res(v.w));
            g_apx[ap_idx(row, lane)] = pack_row_frag(hx, hy, lx, ly, lane);
        }
    }
}

// ---------------- CSR construction -----------------------------------------
__global__ void k_zero() {
    int i = blockIdx.x * blockDim.x + threadIdx.x;
    if (i < NN) { g_deg[i] = 0; g_cursor[i] = 0; }
}
__global__ void k_hist(const int* __restrict__ ei) {
    int e = blockIdx.x * blockDim.x + threadIdx.x;
    if (e < EE) atomicAdd(&g_deg[ei[EE + e]], 1);
}
__global__ void k_scan_block() {
    __shared__ int sh[SCAN_B];
    int i = blockIdx.x * SCAN_B + threadIdx.x;
    int v = (i < NN) ? g_deg[i] : 0;
    sh[threadIdx.x] = v;
    __syncthreads();
    for (int off = 1; off < SCAN_B; off <<= 1) {
        int t = 0;
        if (threadIdx.x >= off) t = sh[threadIdx.x - off];
        __syncthreads();
        if (threadIdx.x >= off) sh[threadIdx.x] += t;
        __syncthreads();
    }
    if (i < NN) g_incl[i] = sh[threadIdx.x];
    if (threadIdx.x == SCAN_B - 1) g_bsums[blockIdx.x] = sh[SCAN_B - 1];
}
__global__ void k_scan_bsums() {
    __shared__ int sh[128];
    int t = threadIdx.x;
    sh[t] = (t < NB) ? g_bsums[t] : 0;
    __syncthreads();
    for (int off = 1; off < 128; off <<= 1) {
        int v = 0;
        if (t >= off) v = sh[t - off];
        __syncthreads();
        if (t >= off) sh[t] += v;
        __syncthreads();
    }
    if (t < NB) g_bsums[t] = sh[t];
}
__global__ void k_scan_fix() {
    int i = blockIdx.x * SCAN_B + threadIdx.x;
    if (i < NN) {
        int off = (blockIdx.x > 0) ? g_bsums[blockIdx.x - 1] : 0;
        g_rowptr[i + 1] = g_incl[i] + off;
    }
    if (i == 0) g_rowptr[0] = 0;
}
__global__ void k_scatter(const int* __restrict__ ei) {
    int e = blockIdx.x * blockDim.x + threadIdx.x;
    if (e >= EE) return;
    int s = ei[e];
    int d = ei[EE + e];
    int pos = g_rowptr[d] + atomicAdd(&g_cursor[d], 1);
    g_srcs[pos] = s;
}

// ---------------- HMMA GEMM: tile M=128 x N=64 per CTA, K=128, split bf16 --
__global__ __launch_bounds__(256, 3) void mma_gemm(
    const uint4* __restrict__ Ain,
    int wslot, int mode,
    const float* __restrict__ bias,
    const float* __restrict__ attS, const float* __restrict__ attD)
{
    __shared__ uint4 sB[2048];   // 32 KB: this half's B fragments
    const int tid  = threadIdx.x;
    const int warp = tid >> 5;
    const int lane = tid & 31;
    const int g = lane >> 2;
    const int t = lane & 3;
    const int by = blockIdx.y;

    {
        const uint4* bf = g_bfrag + (size_t)wslot * 4096 + (size_t)by * 2048;
#pragma unroll
        for (int i = 0; i < 8; ++i)
            sB[i * 256 + tid] = bf[i * 256 + tid];
    }
    __syncthreads();

    const int tile = blockIdx.x * 8 + warp;              // 16-row tile index
    const int tl = (tile < NTILES) ? tile : (NTILES - 1);
    const int rowg = tile * 16 + g;
    const int rowh = rowg + 8;

    const uint4* __restrict__ at = Ain + (size_t)tl * 512;

    float acc[8][4];
#pragma unroll
    for (int nb = 0; nb < 8; ++nb)
#pragma unroll
        for (int j = 0; j < 4; ++j) acc[nb][j] = 0.f;

#pragma unroll
    for (int ks = 0; ks < 8; ++ks) {
        uint4 Ag  = at[ks * 64 + lane];
        uint4 Ahh = at[ks * 64 + 32 + lane];
#pragma unroll
        for (int nb = 0; nb < 8; ++nb) {
            uint4 b = sB[(nb * 8 + ks) * 32 + lane];
            mma16816(acc[nb][0], acc[nb][1], acc[nb][2], acc[nb][3],
                     Ag.x, Ahh.x, Ag.y, Ahh.y, b.x, b.y);
            mma16816(acc[nb][0], acc[nb][1], acc[nb][2], acc[nb][3],
                     Ag.x, Ahh.x, Ag.y, Ahh.y, b.z, b.w);
            mma16816(acc[nb][0], acc[nb][1], acc[nb][2], acc[nb][3],
                     Ag.z, Ahh.z, Ag.w, Ahh.w, b.x, b.y);
        }
    }

    const bool vg = rowg < NN;
    const bool vh = rowh < NN;

    if (mode == 0) {
        uint4* atw = g_ap + (size_t)tl * 512;
#pragma unroll
        for (int k = 0; k < 4; ++k) {
            const int nb0 = 2 * k, nb1 = 2 * k + 1;
            const int c0 = by * 64 + nb0 * 8 + 2 * t;
            const int c1 = by * 64 + nb1 * 8 + 2 * t;
            float b00 = __ldg(bias + c0), b01 = __ldg(bias + c0 + 1);
            float b10 = __ldg(bias + c1), b11 = __ldg(bias + c1 + 1);
            float f0 = acc[nb0][0] + b00, f1 = acc[nb0][1] + b01;
            float f2 = acc[nb0][2] + b00, f3 = acc[nb0][3] + b01;
            float f4 = acc[nb1][0] + b10, f5 = acc[nb1][1] + b11;
            float f6 = acc[nb1][2] + b10, f7 = acc[nb1][3] + b11;
            f0 = (f0 > 0.f) ? f0 : 0.01f * f0;
            f1 = (f1 > 0.f) ? f1 : 0.01f * f1;
            f2 = (f2 > 0.f) ? f2 : 0.01f * f2;
            f3 = (f3 > 0.f) ? f3 : 0.01f * f3;
            f4 = (f4 > 0.f) ? f4 : 0.01f * f4;
            f5 = (f5 > 0.f) ? f5 : 0.01f * f5;
            f6 = (f6 > 0.f) ? f6 : 0.01f * f6;
            f7 = (f7 > 0.f) ? f7 : 0.01f * f7;
            const int ksl = by * 4 + k;
            if (vg) {
                uint4 o;
                o.x = bf2(f0, f1);
                o.y = bf2(f4, f5);
                o.z = bf2(bf_res(f0), bf_res(f1));
                o.w = bf2(bf_res(f4), bf_res(f5));
                atw[ksl * 64 + g * 4 + t] = o;
            }
            if (vh) {
                uint4 o;
                o.x = bf2(f2, f3);
                o.y = bf2(f6, f7);
                o.z = bf2(bf_res(f2), bf_res(f3));
                o.w = bf2(bf_res(f6), bf_res(f7));
                atw[ksl * 64 + 32 + g * 4 + t] = o;
            }
        }
    } else {
        float sg = 0.f, dg = 0.f, sh = 0.f, dh = 0.f;
        u32* hg = (u32*)g_h2h + (size_t)rowg * 64;
        u32* hh = (u32*)g_h2h + (size_t)rowh * 64;
#pragma unroll
        for (int nb = 0; nb < 8; ++nb) {
            const int c0 = by * 64 + nb * 8 + 2 * t;
            float s0 = __ldg(attS + c0), s1 = __ldg(attS + c0 + 1);
            float d0 = __ldg(attD + c0), d1 = __ldg(attD + c0 + 1);
            float f0 = acc[nb][0], f1 = acc[nb][1];
            float f2 = acc[nb][2], f3 = acc[nb][3];
            sg += f0 * s0 + f1 * s1;
            dg += f0 * d0 + f1 * d1;
            sh += f2 * s0 + f3 * s1;
            dh += f2 * d0 + f3 * d1;
            const int ui = (by * 8 + nb) * 4 + t;
            if (vg) hg[ui] = hf2(f0, f1);
            if (vh) hh[ui] = hf2(f2, f3);
        }
#pragma unroll
        for (int o = 1; o <= 2; o <<= 1) {
            sg += __shfl_xor_sync(0xffffffffu, sg, o);
            dg += __shfl_xor_sync(0xffffffffu, dg, o);
            sh += __shfl_xor_sync(0xffffffffu, sh, o);
            dh += __shfl_xor_sync(0xffffffffu, dh, o);
        }
        if (t == 0) {
            if (vg) { g_as2[rowg * 2 + by] = sg; g_ad2[rowg * 2 + by] = dg; }
            if (vh) { g_as2[rowh * 2 + by] = sh; g_ad2[rowh * 2 + by] = dh; }
        }
    }
}

// ------- warp-per-node softmax aggregate -------------------------------------
// Pass A: per-edge weights computed once; (w,src) cached in SMEM (deg<=WCAP,
// which covers all nodes of a Poisson(16) degree distribution) — no global
// round-trip. Fallback to g_ews for deg>WCAP (warp-uniform branch).
// Pass B: 8 edges/iter; (w,src) read via 29-cyc LDS directly ahead of each gather.
__global__ __launch_bounds__(256) void k_agg(
    const float* __restrict__ bias, const float* __restrict__ gamma,
    const float* __restrict__ beta, float* __restrict__ outf)
{
    __shared__ float s_w[8][WCAP];
    __shared__ int   s_s[8][WCAP];
    __shared__ u32 s_hi[8][64];
    __shared__ u32 s_lo[8][64];

    const int warp = threadIdx.x >> 5;
    const int v = (blockIdx.x * blockDim.x + threadIdx.x) >> 5;
    const int lane = threadIdx.x & 31;
    if (v >= NN) return;

    const int beg = g_rowptr[v];
    const int end = g_rowptr[v + 1];
    const int deg = end - beg;
    float2 adp = ((const float2*)g_ad2)[v];
    const float adv = adp.x + adp.y;
    const bool incache = (deg <= WCAP);

    // pass A: weights + denominator
    float dn = 0.f;
    for (int j = beg + lane; j < end; j += 32) {
        int s = g_srcs[j];
        float2 ap = ((const float2*)g_as2)[s];
        float e = ap.x + ap.y + adv;
        e = (e > 0.f) ? e : 0.2f * e;
        float w = __expf(e);
        if (incache) {
            s_w[warp][j - beg] = w;
            s_s[warp][j - beg] = s;
        } else {
            uint2 p;
            p.x = __float_as_uint(w);
            p.y = (u32)s;
            g_ews[j] = p;
        }
        dn += w;
    }
#pragma unroll
    for (int o = 16; o > 0; o >>= 1)
        dn += __shfl_xor_sync(0xffffffffu, dn, o);
    const float winv = (deg > 0) ? 1.f / (dn + 1e-16f) : 0.f;
    __syncwarp();

    // pass B: payload accumulate, 8 edges per warp iteration
    const int part = lane & 15;
    const int eid = lane >> 4;
    float acc[8];
#pragma unroll
    for (int i = 0; i < 8; ++i) acc[i] = 0.f;

    if (incache) {
        for (int j0 = 0; j0 < deg; j0 += 8) {
            float w[4];
            uint4 hv[4];
#pragma unroll
            for (int q = 0; q < 4; ++q) {
                const int j = j0 + 2 * q + eid;
                const bool val = j < deg;
                const int jj = val ? j : 0;
                w[q] = val ? s_w[warp][jj] * winv : 0.f;
                int s = s_s[warp][jj];
                hv[q] = ((const uint4*)g_h2h)[(size_t)s * 16 + part];
            }
#pragma unroll
            for (int q = 0; q < 4; ++q) {
                float2 f0 = __half22float2(*reinterpret_cast<__half2*>(&hv[q].x));
                float2 f1 = __half22float2(*reinterpret_cast<__half2*>(&hv[q].y));
                float2 f2 = __half22float2(*reinterpret_cast<__half2*>(&hv[q].z));
                float2 f3 = __half22float2(*reinterpret_cast<__half2*>(&hv[q].w));
                acc[0] += w[q] * f0.x; acc[1] += w[q] * f0.y;
                acc[2] += w[q] * f1.x; acc[3] += w[q] * f1.y;
                acc[4] += w[q] * f2.x; acc[5] += w[q] * f2.y;
                acc[6] += w[q] * f3.x; acc[7] += w[q] * f3.y;
            }
        }
    } else {
        for (int j0 = beg; j0 < end; j0 += 8) {
            float w[4];
            uint4 hv[4];
#pragma unroll
            for (int q = 0; q < 4; ++q) {
                const int j = j0 + 2 * q + eid;
                const bool val = j < end;
                uint2 ws = g_ews[val ? j : beg];
                w[q] = val ? __uint_as_float(ws.x) * winv : 0.f;
                hv[q] = ((const uint4*)g_h2h)[(size_t)(int)ws.y * 16 + part];
            }
#pragma unroll
            for (int q = 0; q < 4; ++q) {
                float2 f0 = __half22float2(*reinterpret_cast<__half2*>(&hv[q].x));
                float2 f1 = __half22float2(*reinterpret_cast<__half2*>(&hv[q].y));
                float2 f2 = __half22float2(*reinterpret_cast<__half2*>(&hv[q].z));
                float2 f3 = __half22float2(*reinterpret_cast<__half2*>(&hv[q].w));
                acc[0] += w[q] * f0.x; acc[1] += w[q] * f0.y;
                acc[2] += w[q] * f1.x; acc[3] += w[q] * f1.y;
                acc[4] += w[q] * f2.x; acc[5] += w[q] * f2.y;
                acc[6] += w[q] * f3.x; acc[7] += w[q] * f3.y;
            }
        }
    }
    // merge the two edge groups (lane ^ 16 holds the same columns)
#pragma unroll
    for (int i = 0; i < 8; ++i)
        acc[i] += __shfl_xor_sync(0xffffffffu, acc[i], 16);

    // + bias (cols 8*part .. 8*part+7)
    float4 b40 = ((const float4*)bias)[2 * part];
    float4 b41 = ((const float4*)bias)[2 * part + 1];
    acc[0] += b40.x; acc[1] += b40.y; acc[2] += b40.z; acc[3] += b40.w;
    acc[4] += b41.x; acc[5] += b41.y; acc[6] += b41.z; acc[7] += b41.w;

    // LayerNorm over 128 (reduce across the 16-lane group)
    float sum = 0.f, sq = 0.f;
#pragma unroll
    for (int i = 0; i < 8; ++i) { sum += acc[i]; sq += acc[i] * acc[i]; }
#pragma unroll
    for (int o = 1; o < 16; o <<= 1) {
        sum += __shfl_xor_sync(0xffffffffu, sum, o);
        sq  += __shfl_xor_sync(0xffffffffu, sq, o);
    }
    const float mu = sum * (1.f / 128.f);
    const float var = sq * (1.f / 128.f) - mu * mu;
    const float rstd = rsqrtf(var + 1e-5f);

    float4 g40 = ((const float4*)gamma)[2 * part];
    float4 g41 = ((const float4*)gamma)[2 * part + 1];
    float4 e40 = ((const float4*)beta)[2 * part];
    float4 e41 = ((const float4*)beta)[2 * part + 1];
    float gm[8] = {g40.x, g40.y, g40.z, g40.w, g41.x, g41.y, g41.z, g41.w};
    float bt[8] = {e40.x, e40.y, e40.z, e40.w, e41.x, e41.y, e41.z, e41.w};

    float o8[8];
#pragma unroll
    for (int i = 0; i < 8; ++i) {
        float t = (acc[i] - mu) * rstd * gm[i] + bt[i];
        o8[i] = (t > 0.f) ? t : 0.01f * t;
    }

    if (outf) {
        if (eid == 0) {
            float4* dst = (float4*)(outf + (size_t)v * 128);
            dst[2 * part]     = make_float4(o8[0], o8[1], o8[2], o8[3]);
            dst[2 * part + 1] = make_float4(o8[4], o8[5], o8[6], o8[7]);
        }
    } else {
        if (eid == 0) {
#pragma unroll
            for (int q = 0; q < 4; ++q) {
                float a = o8[2 * q], b = o8[2 * q + 1];
                s_hi[warp][4 * part + q] = bf2(a, b);
                s_lo[warp][4 * part + q] = bf2(bf_res(a), bf_res(b));
            }
        }
        __syncwarp();
        const int ks = lane >> 2;
        const int t = lane & 3;
        const int kw = ks * 8 + t;
        uint4 o;
        o.x = s_hi[warp][kw];
        o.y = s_hi[warp][kw + 4];
        o.z = s_lo[warp][kw];
        o.w = s_lo[warp][kw + 4];
        g_ap[ap_idx(v, lane)] = o;
    }
}

// ---------------- launcher --------------------------------------------------
extern "C" void kernel_launch(void* const* d_in, const int* in_sizes, int n_in,
                              void* d_out, int out_size) {
    const float* x       = (const float*)d_in[0];
    const int*   ei      = (const int*)  d_in[1];
    const float* W_in    = (const float*)d_in[2];
    const float* b_in    = (const float*)d_in[3];
    const float* Wl      = (const float*)d_in[4];
    const float* att_src = (const float*)d_in[5];
    const float* att_dst = (const float*)d_in[6];
    const float* bias_l  = (const float*)d_in[7];
    const float* gamma   = (const float*)d_in[8];
    const float* beta    = (const float*)d_in[9];
    float* out = (float*)d_out;

    uint4 *pap = nullptr, *papx = nullptr;
    cudaGetSymbolAddress((void**)&pap, g_ap);
    cudaGetSymbolAddress((void**)&papx, g_apx);

    // side stream + fork/join events (created once; capture-legal pattern)
    static cudaStream_t s2 = nullptr;
    static cudaEvent_t evFork = nullptr, evJoin = nullptr;
    if (!s2) {
        cudaStreamCreateWithFlags(&s2, cudaStreamNonBlocking);
        cudaEventCreateWithFlags(&evFork, cudaEventDisableTiming);
        cudaEventCreateWithFlags(&evJoin, cudaEventDisableTiming);
    }

    const dim3 gemm_grid((NN + 127) / 128, 2);        // 782 x 2
    const int node_warp_blocks = (NN + 7) / 8;        // 12500
    const int setup_blocks = 80 + 12500;              // 12580

    // fork: CSR build on side stream, overlapped with setup + first two GEMMs
    cudaEventRecord(evFork, 0);
    cudaStreamWaitEvent(s2, evFork, 0);
    k_zero<<<(NN + 1023) / 1024, 1024, 0, s2>>>();
    k_hist<<<(EE + 255) / 256, 256, 0, s2>>>(ei);
    k_scan_block<<<NB, SCAN_B, 0, s2>>>();
    k_scan_bsums<<<1, 128, 0, s2>>>();
    k_scan_fix<<<NB, SCAN_B, 0, s2>>>();
    k_scatter<<<(EE + 255) / 256, 256, 0, s2>>>(ei);
    cudaEventRecord(evJoin, s2);

    // main stream: setup -> input projection -> layer-0 mode-1 GEMM
    k_setup<<<setup_blocks, 256>>>(x, W_in, Wl);
    mma_gemm<<<gemm_grid, 256>>>(papx, 0, 0, b_in, nullptr, nullptr);
    mma_gemm<<<gemm_grid, 256>>>(pap, 1, 1, nullptr, att_src, att_dst);

    // join: k_agg needs the CSR
    cudaStreamWaitEvent(0, evJoin, 0);

    for (int i = 0; i < 4; i++) {
        if (i > 0)
            mma_gemm<<<gemm_grid, 256>>>(pap, i + 1, 1, nullptr,
                                         att_src + i * 128, att_dst + i * 128);
        float* dst = (i == 3) ? out : nullptr;
        k_agg<<<node_warp_blocks, 256>>>(bias_l + i * 128, gamma + i * 128,
                                         beta + i * 128, dst);
    }
}

// round 15
// speedup vs baseline: 1.2243x; 1.2243x over previous
#include <cuda_runtime.h>
#include <cuda_fp16.h>
#include <cuda_bf16.h>
#include <cstdint>

#define NN 100000
#define EE 1600000
#define SCAN_B 1024
#define NB ((NN + SCAN_B - 1) / SCAN_B)   // 98
#define NTILES (NN / 16)                  // 6250 (NN divisible by 16)

typedef unsigned long long u64;
typedef unsigned int u32;

// ---------------- scratch (device globals; no allocation allowed) ----------
// A operand (fp16) in 16-row-tile-major fragment layout (uint2 units):
// addr(row, slot) = (row>>4)*512 + (slot>>2)*64 + (row&15)*4 + (slot&3)
// slot = ks*4+t holds uint2{ h[kw], h[kw+4] }, kw = ks*8+t (h = half2 col pairs)
__device__ uint2 g_ap[NN * 32];            // h fragments (GEMM A, layers 1..4)
__device__ uint2 g_apx[NN * 32];           // x fragments (input projection source)
__device__ uint2 g_bfrag[5 * 16 * 8 * 32]; // W fragments: {bh0, bh1} fp16 per lane
__device__ uint2 g_h2h[NN * 32];           // fp16 copy of h2 rows
__device__ float g_as2[NN * 2];            // att-src dot, per N-half partial
__device__ float g_ad2[NN * 2];            // att-dst dot, per N-half partial
__device__ uint2 g_ews[EE];                // {exp-weight bits, src} per CSR slot
__device__ int   g_deg[NN];
__device__ int   g_incl[NN];
__device__ int   g_cursor[NN];
__device__ int   g_rowptr[NN + 1];
__device__ int   g_srcs[EE];
__device__ int   g_bsums[128];

// ---------------- small helpers --------------------------------------------
__device__ __forceinline__ u32 hf2(float a, float b) {
    __half2 t = __floats2half2_rn(a, b);
    return *reinterpret_cast<u32*>(&t);
}
__device__ __forceinline__ size_t ap2_idx(int row, int slot) {
    return (size_t)(row >> 4) * 512 + (size_t)((slot >> 2) << 6)
         + (size_t)((row & 15) << 2) + (size_t)(slot & 3);
}

// Shuffle a row (lane l owns half2 cols j = 2l, 2l+1 as hx, hy) into the
// fp16 fragment uint2 for this lane's slot (ks = l>>2, t = l&3), kw = 8ks+t.
__device__ __forceinline__ uint2 pack_row_frag16(u32 hx, u32 hy, int lane) {
    const int src0 = ((lane >> 2) << 2) + ((lane & 3) >> 1);  // kw>>1
    const int sel = lane & 1;                                  // kw&1
    u32 h0a = __shfl_sync(0xffffffffu, hx, src0);
    u32 h0b = __shfl_sync(0xffffffffu, hy, src0);
    u32 h1a = __shfl_sync(0xffffffffu, hx, src0 + 2);
    u32 h1b = __shfl_sync(0xffffffffu, hy, src0 + 2);
    uint2 r;
    r.x = sel ? h0b : h0a;
    r.y = sel ? h1b : h1a;
    return r;
}

// mma.sync m16n8k16 fp16 x fp32-acc (baseline sm_80+ instruction)
__device__ __forceinline__ void mma16816f(
    float& c0, float& c1, float& c2, float& c3,
    u32 a0, u32 a1, u32 a2, u32 a3, u32 b0, u32 b1)
{
    asm volatile(
        "mma.sync.aligned.m16n8k16.row.col.f32.f16.f16.f32 "
        "{%0,%1,%2,%3}, {%4,%5,%6,%7}, {%8,%9}, {%0,%1,%2,%3};"
        : "+f"(c0), "+f"(c1), "+f"(c2), "+f"(c3)
        : "r"(a0), "r"(a1), "r"(a2), "r"(a3), "r"(b0), "r"(b1));
}

// ---------------- fused setup: W fragments + x conversion -------------------
// block ranges: [0,80) prep_bfrag; [80, 80+12500) convert_x.
__global__ __launch_bounds__(256) void k_setup(
    const float* __restrict__ x,
    const float* __restrict__ W_in, const float* __restrict__ Wl)
{
    const int bid = blockIdx.x;
    const int tid = threadIdx.x;
    if (bid < 80) {
        int idx = bid * 256 + tid;                 // over 20480
        int lane = idx & 31;
        int ks = (idx >> 5) & 7;
        int nb = (idx >> 8) & 15;
        int l = idx >> 12;
        int g = lane >> 2;
        int t = lane & 3;
        int n = nb * 8 + g;
        int kw = ks * 8 + t;
        const float* W = (l == 0) ? W_in : (Wl + (size_t)(l - 1) * 16384);
        float v00 = W[(2 * kw) * 128 + n];
        float v01 = W[(2 * kw + 1) * 128 + n];
        float v10 = W[(2 * kw + 8) * 128 + n];
        float v11 = W[(2 * kw + 9) * 128 + n];
        uint2 f;
        f.x = hf2(v00, v01);
        f.y = hf2(v10, v11);
        g_bfrag[idx] = f;
    } else {
        int row = ((bid - 80) << 3) + (tid >> 5);  // 8 rows per block
        int lane = tid & 31;
        if (row < NN) {
            float4 v = ((const float4*)x)[(size_t)row * 32 + lane];
            u32 hx = hf2(v.x, v.y), hy = hf2(v.z, v.w);
            g_apx[ap2_idx(row, lane)] = pack_row_frag16(hx, hy, lane);
        }
    }
}

// ---------------- CSR construction -----------------------------------------
__global__ void k_zero() {
    int i = blockIdx.x * blockDim.x + threadIdx.x;
    if (i < NN) { g_deg[i] = 0; g_cursor[i] = 0; }
}
__global__ void k_hist(const int* __restrict__ ei) {
    int e = blockIdx.x * blockDim.x + threadIdx.x;
    if (e < EE) atomicAdd(&g_deg[ei[EE + e]], 1);
}
__global__ void k_scan_block() {
    __shared__ int sh[SCAN_B];
    int i = blockIdx.x * SCAN_B + threadIdx.x;
    int v = (i < NN) ? g_deg[i] : 0;
    sh[threadIdx.x] = v;
    __syncthreads();
    for (int off = 1; off < SCAN_B; off <<= 1) {
        int t = 0;
        if (threadIdx.x >= off) t = sh[threadIdx.x - off];
        __syncthreads();
        if (threadIdx.x >= off) sh[threadIdx.x] += t;
        __syncthreads();
    }
    if (i < NN) g_incl[i] = sh[threadIdx.x];
    if (threadIdx.x == SCAN_B - 1) g_bsums[blockIdx.x] = sh[SCAN_B - 1];
}
__global__ void k_scan_bsums() {
    __shared__ int sh[128];
    int t = threadIdx.x;
    sh[t] = (t < NB) ? g_bsums[t] : 0;
    __syncthreads();
    for (int off = 1; off < 128; off <<= 1) {
        int v = 0;
        if (t >= off) v = sh[t - off];
        __syncthreads();
        if (t >= off) sh[t] += v;
        __syncthreads();
    }
    if (t < NB) g_bsums[t] = sh[t];
}
__global__ void k_scan_fix() {
    int i = blockIdx.x * SCAN_B + threadIdx.x;
    if (i < NN) {
        int off = (blockIdx.x > 0) ? g_bsums[blockIdx.x - 1] : 0;
        g_rowptr[i + 1] = g_incl[i] + off;
    }
    if (i == 0) g_rowptr[0] = 0;
}
__global__ void k_scatter(const int* __restrict__ ei) {
    int e = blockIdx.x * blockDim.x + threadIdx.x;
    if (e >= EE) return;
    int s = ei[e];
    int d = ei[EE + e];
    int pos = g_rowptr[d] + atomicAdd(&g_cursor[d], 1);
    g_srcs[pos] = s;
}

// ---------------- HMMA GEMM: tile M=128 x N=64 per CTA, K=128, fp16 --------
// grid (782, 2). 8 warps x 16 rows x 64 cols; ONE fp16 MMA per (ks, nb).
__global__ __launch_bounds__(256, 4) void mma_gemm(
    const uint2* __restrict__ Ain,
    int wslot, int mode,
    const float* __restrict__ bias,
    const float* __restrict__ attS, const float* __restrict__ attD)
{
    __shared__ uint2 sB[2048];   // 16 KB: this half's B fragments
    const int tid  = threadIdx.x;
    const int warp = tid >> 5;
    const int lane = tid & 31;
    const int g = lane >> 2;
    const int t = lane & 3;
    const int by = blockIdx.y;

    {
        const uint2* bf = g_bfrag + (size_t)wslot * 4096 + (size_t)by * 2048;
#pragma unroll
        for (int i = 0; i < 8; ++i)
            sB[i * 256 + tid] = bf[i * 256 + tid];
    }
    __syncthreads();

    const int tile = blockIdx.x * 8 + warp;              // 16-row tile index
    const int tl = (tile < NTILES) ? tile : (NTILES - 1);
    const int rowg = tile * 16 + g;
    const int rowh = rowg + 8;

    const uint2* __restrict__ at = Ain + (size_t)tl * 512;

    float acc[8][4];
#pragma unroll
    for (int nb = 0; nb < 8; ++nb)
#pragma unroll
        for (int j = 0; j < 4; ++j) acc[nb][j] = 0.f;

#pragma unroll
    for (int ks = 0; ks < 8; ++ks) {
        uint2 Ag  = at[ks * 64 + lane];        // row tile*16+g,   slot ks*4+t
        uint2 Ahh = at[ks * 64 + 32 + lane];   // row tile*16+8+g, slot ks*4+t
#pragma unroll
        for (int nb = 0; nb < 8; ++nb) {
            uint2 b = sB[(nb * 8 + ks) * 32 + lane];
            mma16816f(acc[nb][0], acc[nb][1], acc[nb][2], acc[nb][3],
                      Ag.x, Ahh.x, Ag.y, Ahh.y, b.x, b.y);
        }
    }

    const bool vg = rowg < NN;
    const bool vh = rowh < NN;

    if (mode == 0) {
        // tile-major fp16 fragment writes: 256 B contiguous per k per row-half
        uint2* atw = g_ap + (size_t)tl * 512;
#pragma unroll
        for (int k = 0; k < 4; ++k) {
            const int nb0 = 2 * k, nb1 = 2 * k + 1;
            const int c0 = by * 64 + nb0 * 8 + 2 * t;
            const int c1 = by * 64 + nb1 * 8 + 2 * t;
            float b00 = __ldg(bias + c0), b01 = __ldg(bias + c0 + 1);
            float b10 = __ldg(bias + c1), b11 = __ldg(bias + c1 + 1);
            float f0 = acc[nb0][0] + b00, f1 = acc[nb0][1] + b01;
            float f2 = acc[nb0][2] + b00, f3 = acc[nb0][3] + b01;
            float f4 = acc[nb1][0] + b10, f5 = acc[nb1][1] + b11;
            float f6 = acc[nb1][2] + b10, f7 = acc[nb1][3] + b11;
            f0 = (f0 > 0.f) ? f0 : 0.01f * f0;
            f1 = (f1 > 0.f) ? f1 : 0.01f * f1;
            f2 = (f2 > 0.f) ? f2 : 0.01f * f2;
            f3 = (f3 > 0.f) ? f3 : 0.01f * f3;
            f4 = (f4 > 0.f) ? f4 : 0.01f * f4;
            f5 = (f5 > 0.f) ? f5 : 0.01f * f5;
            f6 = (f6 > 0.f) ? f6 : 0.01f * f6;
            f7 = (f7 > 0.f) ? f7 : 0.01f * f7;
            const int ksl = by * 4 + k;   // slot>>2 for this k
            if (vg) {
                uint2 o;
                o.x = hf2(f0, f1);
                o.y = hf2(f4, f5);
                atw[ksl * 64 + g * 4 + t] = o;
            }
            if (vh) {
                uint2 o;
                o.x = hf2(f2, f3);
                o.y = hf2(f6, f7);
                atw[ksl * 64 + 32 + g * 4 + t] = o;
            }
        }
    } else {
        float sg = 0.f, dg = 0.f, sh = 0.f, dh = 0.f;
        u32* hg = (u32*)g_h2h + (size_t)rowg * 64;
        u32* hh = (u32*)g_h2h + (size_t)rowh * 64;
#pragma unroll
        for (int nb = 0; nb < 8; ++nb) {
            const int c0 = by * 64 + nb * 8 + 2 * t;
            float s0 = __ldg(attS + c0), s1 = __ldg(attS + c0 + 1);
            float d0 = __ldg(attD + c0), d1 = __ldg(attD + c0 + 1);
            float f0 = acc[nb][0], f1 = acc[nb][1];
            float f2 = acc[nb][2], f3 = acc[nb][3];
            sg += f0 * s0 + f1 * s1;
            dg += f0 * d0 + f1 * d1;
            sh += f2 * s0 + f3 * s1;
            dh += f2 * d0 + f3 * d1;
            const int ui = (by * 8 + nb) * 4 + t;
            if (vg) hg[ui] = hf2(f0, f1);
            if (vh) hh[ui] = hf2(f2, f3);
        }
#pragma unroll
        for (int o = 1; o <= 2; o <<= 1) {
            sg += __shfl_xor_sync(0xffffffffu, sg, o);
            dg += __shfl_xor_sync(0xffffffffu, dg, o);
            sh += __shfl_xor_sync(0xffffffffu, sh, o);
            dh += __shfl_xor_sync(0xffffffffu, dh, o);
        }
        if (t == 0) {
            if (vg) { g_as2[rowg * 2 + by] = sg; g_ad2[rowg * 2 + by] = dg; }
            if (vh) { g_as2[rowh * 2 + by] = sh; g_ad2[rowh * 2 + by] = dh; }
        }
    }
}

// ------- warp-per-node softmax aggregate (R13 structure) ---------------------
__global__ __launch_bounds__(256) void k_agg(
    const float* __restrict__ bias, const float* __restrict__ gamma,
    const float* __restrict__ beta, float* __restrict__ outf)
{
    __shared__ u32 s_hi[8][64];

    const int warp = threadIdx.x >> 5;
    const int v = (blockIdx.x * blockDim.x + threadIdx.x) >> 5;
    const int lane = threadIdx.x & 31;
    if (v >= NN) return;

    const int beg = g_rowptr[v];
    const int end = g_rowptr[v + 1];
    float2 adp = ((const float2*)g_ad2)[v];
    const float adv = adp.x + adp.y;

    // pass A: fused weight+src stream, denominator
    float dn = 0.f;
    for (int j = beg + lane; j < end; j += 32) {
        int s = g_srcs[j];
        float2 ap = ((const float2*)g_as2)[s];
        float e = ap.x + ap.y + adv;
        e = (e > 0.f) ? e : 0.2f * e;
        float w = __expf(e);
        uint2 p;
        p.x = __float_as_uint(w);
        p.y = (u32)s;
        g_ews[j] = p;
        dn += w;
    }
#pragma unroll
    for (int o = 16; o > 0; o >>= 1)
        dn += __shfl_xor_sync(0xffffffffu, dn, o);
    const float winv = (end > beg) ? 1.f / (dn + 1e-16f) : 0.f;

    // pass B: payload accumulate, 8 edges/iter with ews prefetch
    const int part = lane & 15;
    const int eid = lane >> 4;
    float acc[8];
#pragma unroll
    for (int i = 0; i < 8; ++i) acc[i] = 0.f;

    uint2 cur[4];
#pragma unroll
    for (int q = 0; q < 4; ++q) {
        int j = beg + 2 * q + eid;
        cur[q] = g_ews[(j < end) ? j : beg];
    }

    for (int j0 = beg; j0 < end; j0 += 8) {
        float w[4];
        uint4 hv[4];
#pragma unroll
        for (int q = 0; q < 4; ++q) {
            const int j = j0 + 2 * q + eid;
            w[q] = (j < end) ? __uint_as_float(cur[q].x) * winv : 0.f;
            hv[q] = ((const uint4*)g_h2h)[(size_t)(int)cur[q].y * 16 + part];
        }
        uint2 nxt[4];
#pragma unroll
        for (int q = 0; q < 4; ++q) {
            int j = j0 + 8 + 2 * q + eid;
            nxt[q] = g_ews[(j < end) ? j : beg];
        }
#pragma unroll
        for (int q = 0; q < 4; ++q) {
            float2 f0 = __half22float2(*reinterpret_cast<__half2*>(&hv[q].x));
            float2 f1 = __half22float2(*reinterpret_cast<__half2*>(&hv[q].y));
            float2 f2 = __half22float2(*reinterpret_cast<__half2*>(&hv[q].z));
            float2 f3 = __half22float2(*reinterpret_cast<__half2*>(&hv[q].w));
            acc[0] += w[q] * f0.x; acc[1] += w[q] * f0.y;
            acc[2] += w[q] * f1.x; acc[3] += w[q] * f1.y;
            acc[4] += w[q] * f2.x; acc[5] += w[q] * f2.y;
            acc[6] += w[q] * f3.x; acc[7] += w[q] * f3.y;
        }
#pragma unroll
        for (int q = 0; q < 4; ++q) cur[q] = nxt[q];
    }
#pragma unroll
    for (int i = 0; i < 8; ++i)
        acc[i] += __shfl_xor_sync(0xffffffffu, acc[i], 16);

    float4 b40 = ((const float4*)bias)[2 * part];
    float4 b41 = ((const float4*)bias)[2 * part + 1];
    acc[0] += b40.x; acc[1] += b40.y; acc[2] += b40.z; acc[3] += b40.w;
    acc[4] += b41.x; acc[5] += b41.y; acc[6] += b41.z; acc[7] += b41.w;

    float sum = 0.f, sq = 0.f;
#pragma unroll
    for (int i = 0; i < 8; ++i) { sum += acc[i]; sq += acc[i] * acc[i]; }
#pragma unroll
    for (int o = 1; o < 16; o <<= 1) {
        sum += __shfl_xor_sync(0xffffffffu, sum, o);
        sq  += __shfl_xor_sync(0xffffffffu, sq, o);
    }
    const float mu = sum * (1.f / 128.f);
    const float var = sq * (1.f / 128.f) - mu * mu;
    const float rstd = rsqrtf(var + 1e-5f);

    float4 g40 = ((const float4*)gamma)[2 * part];
    float4 g41 = ((const float4*)gamma)[2 * part + 1];
    float4 e40 = ((const float4*)beta)[2 * part];
    float4 e41 = ((const float4*)beta)[2 * part + 1];
    float gm[8] = {g40.x, g40.y, g40.z, g40.w, g41.x, g41.y, g41.z, g41.w};
    float bt[8] = {e40.x, e40.y, e40.z, e40.w, e41.x, e41.y, e41.z, e41.w};

    float o8[8];
#pragma unroll
    for (int i = 0; i < 8; ++i) {
        float t = (acc[i] - mu) * rstd * gm[i] + bt[i];
        o8[i] = (t > 0.f) ? t : 0.01f * t;
    }

    if (outf) {
        if (eid == 0) {
            float4* dst = (float4*)(outf + (size_t)v * 128);
            dst[2 * part]     = make_float4(o8[0], o8[1], o8[2], o8[3]);
            dst[2 * part + 1] = make_float4(o8[4], o8[5], o8[6], o8[7]);
        }
    } else {
        // stage fp16 col-pairs in smem, read back in fragment order
        if (eid == 0) {
#pragma unroll
            for (int q = 0; q < 4; ++q)
                s_hi[warp][4 * part + q] = hf2(o8[2 * q], o8[2 * q + 1]);
        }
        __syncwarp();
        const int ks = lane >> 2;
        const int t = lane & 3;
        const int kw = ks * 8 + t;
        uint2 o;
        o.x = s_hi[warp][kw];
        o.y = s_hi[warp][kw + 4];
        g_ap[ap2_idx(v, lane)] = o;
    }
}

// ---------------- launcher --------------------------------------------------
extern "C" void kernel_launch(void* const* d_in, const int* in_sizes, int n_in,
                              void* d_out, int out_size) {
    const float* x       = (const float*)d_in[0];
    const int*   ei      = (const int*)  d_in[1];
    const float* W_in    = (const float*)d_in[2];
    const float* b_in    = (const float*)d_in[3];
    const float* Wl      = (const float*)d_in[4];
    const float* att_src = (const float*)d_in[5];
    const float* att_dst = (const float*)d_in[6];
    const float* bias_l  = (const float*)d_in[7];
    const float* gamma   = (const float*)d_in[8];
    const float* beta    = (const float*)d_in[9];
    float* out = (float*)d_out;

    uint2 *pap = nullptr, *papx = nullptr;
    cudaGetSymbolAddress((void**)&pap, g_ap);
    cudaGetSymbolAddress((void**)&papx, g_apx);

    // side stream + fork/join events (created once; capture-legal pattern)
    static cudaStream_t s2 = nullptr;
    static cudaEvent_t evFork = nullptr, evJoin = nullptr;
    if (!s2) {
        cudaStreamCreateWithFlags(&s2, cudaStreamNonBlocking);
        cudaEventCreateWithFlags(&evFork, cudaEventDisableTiming);
        cudaEventCreateWithFlags(&evJoin, cudaEventDisableTiming);
    }

    const dim3 gemm_grid((NN + 127) / 128, 2);        // 782 x 2
    const int node_warp_blocks = (NN + 7) / 8;        // 12500
    const int setup_blocks = 80 + 12500;              // 12580

    // fork: CSR build on side stream, overlapped with setup + first two GEMMs
    cudaEventRecord(evFork, 0);
    cudaStreamWaitEvent(s2, evFork, 0);
    k_zero<<<(NN + 1023) / 1024, 1024, 0, s2>>>();
    k_hist<<<(EE + 255) / 256, 256, 0, s2>>>(ei);
    k_scan_block<<<NB, SCAN_B, 0, s2>>>();
    k_scan_bsums<<<1, 128, 0, s2>>>();
    k_scan_fix<<<NB, SCAN_B, 0, s2>>>();
    k_scatter<<<(EE + 255) / 256, 256, 0, s2>>>(ei);
    cudaEventRecord(evJoin, s2);

    // main stream: setup -> input projection -> layer-0 mode-1 GEMM
    k_setup<<<setup_blocks, 256>>>(x, W_in, Wl);
    mma_gemm<<<gemm_grid, 256>>>(papx, 0, 0, b_in, nullptr, nullptr);
    mma_gemm<<<gemm_grid, 256>>>(pap, 1, 1, nullptr, att_src, att_dst);

    // join: k_agg needs the CSR
    cudaStreamWaitEvent(0, evJoin, 0);

    for (int i = 0; i < 4; i++) {
        if (i > 0)
            mma_gemm<<<gemm_grid, 256>>>(pap, i + 1, 1, nullptr,
                                         att_src + i * 128, att_dst + i * 128);
        float* dst = (i == 3) ? out : nullptr;
        k_agg<<<node_warp_blocks, 256>>>(bias_l + i * 128, gamma + i * 128,
                                         beta + i * 128, dst);
    }
}